// round 2
// baseline (speedup 1.0000x reference)
#include <cuda_runtime.h>
#include <math.h>
#include <stdint.h>

// ---------------- problem constants ----------------
#define HDIM  384
#define HHALF 192
constexpr int   MAXN   = 40000;
constexpr int   MAXD   = 20000;
constexpr int   MAXE   = 800000;
constexpr int   MAXNNZ = 800000;
constexpr float ALPHA  = 0.65f;
constexpr float LN_EPS = 1e-5f;

// ---------------- static scratch (no allocation allowed) ----------------
__device__ float g_buf1[(size_t)MAXN * HDIM];
__device__ float g_buf2[(size_t)MAXN * HDIM];
__device__ float g_docH [(size_t)MAXD * HDIM];
__device__ float g_docH0[(size_t)MAXD * HDIM];
__device__ float g_hidden[(size_t)MAXD * HDIM];
__device__ float g_doc  [(size_t)MAXD * HDIM];
__device__ float g_t2   [(size_t)MAXD * HHALF];

__device__ int   g_Arp[MAXN + 1];
__device__ int   g_Awp[MAXN + 1];
__device__ int   g_Aci[MAXE];
__device__ float g_Av [MAXE];
__device__ int   g_Xrp[MAXD + 1];
__device__ int   g_Xwp[MAXD + 1];
__device__ int   g_Xci[MAXNNZ];
__device__ float g_Xv [MAXNNZ];

// ---------------- small device helpers ----------------
__device__ __forceinline__ float gelu_exact(float x) {
    return 0.5f * x * (1.0f + erff(x * 0.70710678118654752f));
}
__device__ __forceinline__ float sigmoidf_(float x) {
    return 1.0f / (1.0f + __expf(-x));
}

// ---------------- CSR build ----------------
__global__ void k_zero_i32(int* p, int n) {
    int i = blockIdx.x * blockDim.x + threadIdx.x;
    if (i < n) p[i] = 0;
}

__global__ void k_hist(const int* __restrict__ rows, int ne, int* __restrict__ cnt) {
    int e = blockIdx.x * blockDim.x + threadIdx.x;
    if (e < ne) atomicAdd(&cnt[rows[e]], 1);
}

// single-block chunked exclusive scan over counts[0..n-1]; writes offsets in
// place, a copy to wp[], and data[n] = total.
__global__ void k_scan_excl(int* __restrict__ data, int n, int* __restrict__ wp) {
    __shared__ int sums[1024];
    int t = threadIdx.x;
    int C = (n + 1023) / 1024;
    int start = t * C;
    int end   = min(start + C, n);

    int s = 0;
    for (int i = start; i < end; i++) s += data[i];
    sums[t] = s;
    __syncthreads();

    for (int off = 1; off < 1024; off <<= 1) {
        int add = (t >= off) ? sums[t - off] : 0;
        __syncthreads();
        sums[t] += add;
        __syncthreads();
    }

    int run = sums[t] - s;  // exclusive prefix of this chunk
    for (int i = start; i < end; i++) {
        int c = data[i];
        data[i] = run;
        wp[i]   = run;
        run += c;
    }
    if (t == 1023) data[n] = sums[1023];
}

__global__ void k_scatter(const int* __restrict__ rows, const int* __restrict__ cols,
                          const float* __restrict__ vals, int ne,
                          int* __restrict__ wp, int* __restrict__ ci,
                          float* __restrict__ cv) {
    int e = blockIdx.x * blockDim.x + threadIdx.x;
    if (e < ne) {
        int pos = atomicAdd(&wp[rows[e]], 1);
        ci[pos] = cols[e];
        cv[pos] = vals[e];
    }
}

// ---------------- SpMM (CSR, gather, no atomics) ----------------
// one block of 128 threads per output row; each thread owns 3 of 384 columns.
__global__ void k_spmm(const int* __restrict__ rp, const int* __restrict__ ci,
                       const float* __restrict__ cv, const float* __restrict__ M,
                       float* __restrict__ out) {
    int r = blockIdx.x;
    int t = threadIdx.x;
    int s = rp[r], e = rp[r + 1];
    float a0 = 0.f, a1 = 0.f, a2 = 0.f;
    for (int j = s; j < e; j++) {
        float v = cv[j];
        const float* m = M + (size_t)ci[j] * HDIM;
        a0 = fmaf(v, m[t],       a0);
        a1 = fmaf(v, m[t + 128], a1);
        a2 = fmaf(v, m[t + 256], a2);
    }
    float* o = out + (size_t)r * HDIM;
    o[t] = a0; o[t + 128] = a1; o[t + 256] = a2;
}

// ---------------- fused GEMM with epilogues ----------------
// C[M x NCOLS] = epilogue( A[M x K] @ W[K x NCOLS] )
// A may be a virtual concat [A1 | A2] split at K1.
// block tile: 32 rows x NCOLS cols; threads (64,4); each thread: 8 rows x (NCOLS/64) cols.
enum { EPI_LN_GELU = 0, EPI_GELU = 1, EPI_GATE = 2, EPI_GELU_LN = 3 };

template <int NCOLS, int EPI>
__global__ void __launch_bounds__(256)
k_gemm(const float* __restrict__ A1, const float* __restrict__ A2,
       int K, int K1,
       const float* __restrict__ W, const float* __restrict__ bias,
       const float* __restrict__ g, const float* __restrict__ b,
       const float* __restrict__ aux1, const float* __restrict__ aux2,
       const float* __restrict__ res,
       float* __restrict__ out, int M) {
    constexpr int CPT = NCOLS / 64;   // cols per thread (6 or 3)
    constexpr int RPT = 8;            // rows per thread
    __shared__ float As[32][17];
    __shared__ float Ws[16][NCOLS];
    __shared__ float redS[4][RPT][2];
    __shared__ float redQ[4][RPT][2];

    const int tx = threadIdx.x, ty = threadIdx.y;
    const int tid = ty * 64 + tx;
    const int bm0 = blockIdx.x * 32;

    float acc[RPT][CPT];
#pragma unroll
    for (int i = 0; i < RPT; i++)
#pragma unroll
        for (int j = 0; j < CPT; j++) acc[i][j] = 0.f;

    for (int k0 = 0; k0 < K; k0 += 16) {
        // A tile: 32 rows x 16 k (2 elements per thread)
#pragma unroll
        for (int idx = tid; idx < 32 * 16; idx += 256) {
            int row = idx >> 4, kk = idx & 15;
            int k = k0 + kk;
            int grow = bm0 + row;
            float v = 0.f;
            if (grow < M) {
                if (k < K1) v = A1[(size_t)grow * K1 + k];
                else        v = A2[(size_t)grow * (K - K1) + (k - K1)];
            }
            As[row][kk] = v;
        }
        // W tile: 16 x NCOLS
        for (int idx = tid; idx < 16 * NCOLS; idx += 256) {
            int kk = idx / NCOLS;
            int c  = idx - kk * NCOLS;
            Ws[kk][c] = W[(size_t)(k0 + kk) * NCOLS + c];
        }
        __syncthreads();

#pragma unroll
        for (int k = 0; k < 16; k++) {
            float a[RPT], w[CPT];
#pragma unroll
            for (int i = 0; i < RPT; i++) a[i] = As[ty * RPT + i][k];
#pragma unroll
            for (int j = 0; j < CPT; j++) w[j] = Ws[k][tx + j * 64];
#pragma unroll
            for (int i = 0; i < RPT; i++)
#pragma unroll
                for (int j = 0; j < CPT; j++) acc[i][j] = fmaf(a[i], w[j], acc[i][j]);
        }
        __syncthreads();
    }

    if constexpr (EPI == EPI_GELU) {
#pragma unroll
        for (int i = 0; i < RPT; i++) {
            int grow = bm0 + ty * RPT + i;
            if (grow >= M) continue;
#pragma unroll
            for (int j = 0; j < CPT; j++) {
                int col = tx + j * 64;
                float c = acc[i][j] + (bias ? bias[col] : 0.f);
                out[(size_t)grow * NCOLS + col] = gelu_exact(c);
            }
        }
    } else if constexpr (EPI == EPI_GATE) {
#pragma unroll
        for (int i = 0; i < RPT; i++) {
            int grow = bm0 + ty * RPT + i;
            if (grow >= M) continue;
#pragma unroll
            for (int j = 0; j < CPT; j++) {
                int col = tx + j * 64;
                size_t idx = (size_t)grow * NCOLS + col;
                float s = sigmoidf_(acc[i][j] + bias[col]);
                out[idx] = s * aux1[idx] + (1.f - s) * aux2[idx];
            }
        }
    } else {
        // LayerNorm epilogues: row stats over NCOLS (=384)
#pragma unroll
        for (int i = 0; i < RPT; i++) {
            float s = 0.f, q = 0.f;
#pragma unroll
            for (int j = 0; j < CPT; j++) {
                int col = tx + j * 64;
                float v = acc[i][j];
                if constexpr (EPI == EPI_GELU_LN) v = gelu_exact(v + bias[col]);
                acc[i][j] = v;
                s += v;
                q += v * v;
            }
            for (int off = 16; off > 0; off >>= 1) {
                s += __shfl_down_sync(0xffffffffu, s, off);
                q += __shfl_down_sync(0xffffffffu, q, off);
            }
            if ((tx & 31) == 0) {
                redS[ty][i][tx >> 5] = s;
                redQ[ty][i][tx >> 5] = q;
            }
        }
        __syncthreads();
#pragma unroll
        for (int i = 0; i < RPT; i++) {
            int grow = bm0 + ty * RPT + i;
            float sum = redS[ty][i][0] + redS[ty][i][1];
            float qq  = redQ[ty][i][0] + redQ[ty][i][1];
            float mean = sum * (1.0f / NCOLS);
            float var  = qq * (1.0f / NCOLS) - mean * mean;
            float rstd = rsqrtf(var + LN_EPS);
            if (grow >= M) continue;
#pragma unroll
            for (int j = 0; j < CPT; j++) {
                int col = tx + j * 64;
                float nv = (acc[i][j] - mean) * rstd * g[col] + b[col];
                float o;
                if constexpr (EPI == EPI_LN_GELU) {
                    o = gelu_exact(nv);
                    if (res) o = (1.f - ALPHA) * res[(size_t)grow * NCOLS + col] + ALPHA * o;
                } else {
                    o = nv;
                }
                out[(size_t)grow * NCOLS + col] = o;
            }
        }
    }
}

// ---------------- final tiny classifier ----------------
__global__ void k_logits(const float* __restrict__ t2, const float* __restrict__ clsW,
                         const float* __restrict__ clsb, float* __restrict__ out, int D) {
    int warp = (blockIdx.x * blockDim.x + threadIdx.x) >> 5;
    int lane = threadIdx.x & 31;
    if (warp >= D) return;
    const float* r = t2 + (size_t)warp * HHALF;
    float a0 = 0.f, a1 = 0.f;
    for (int k = lane; k < HHALF; k += 32) {
        float x = r[k];
        a0 = fmaf(x, clsW[2 * k],     a0);
        a1 = fmaf(x, clsW[2 * k + 1], a1);
    }
    for (int off = 16; off > 0; off >>= 1) {
        a0 += __shfl_down_sync(0xffffffffu, a0, off);
        a1 += __shfl_down_sync(0xffffffffu, a1, off);
    }
    if (lane == 0) {
        out[2 * warp]     = a0 + clsb[0];
        out[2 * warp + 1] = a1 + clsb[1];
    }
}

// ---------------- launch ----------------
extern "C" void kernel_launch(void* const* d_in, const int* in_sizes, int n_in,
                              void* d_out, int out_size) {
    const int*   A_rows  = (const int*)  d_in[0];
    const int*   A_cols  = (const int*)  d_in[1];
    const float* A_vals  = (const float*)d_in[2];
    const int*   X_rows  = (const int*)  d_in[3];
    const int*   X_cols  = (const int*)  d_in[4];
    const float* X_vals  = (const float*)d_in[5];
    // d_in[6] = num_docs (device scalar; D derived from out_size)
    const float* emb     = (const float*)d_in[7];
    const float* W1      = (const float*)d_in[8];
    const float* W2      = (const float*)d_in[9];
    const float* W3      = (const float*)d_in[10];
    const float* g1      = (const float*)d_in[11];
    const float* b1      = (const float*)d_in[12];
    const float* g2      = (const float*)d_in[13];
    const float* b2      = (const float*)d_in[14];
    const float* g3      = (const float*)d_in[15];
    const float* b3      = (const float*)d_in[16];
    const float* mlp_W1  = (const float*)d_in[17];
    const float* mlp_b1  = (const float*)d_in[18];
    const float* mlp_g   = (const float*)d_in[19];
    const float* mlp_bn  = (const float*)d_in[20];
    const float* mlp_W2  = (const float*)d_in[21];
    const float* mlp_b2  = (const float*)d_in[22];
    const float* cls_W   = (const float*)d_in[23];
    const float* cls_b   = (const float*)d_in[24];
    const float* gate_W1 = (const float*)d_in[25];
    const float* gate_b1 = (const float*)d_in[26];
    const float* gate_W2 = (const float*)d_in[27];
    const float* gate_b2 = (const float*)d_in[28];

    const int E   = in_sizes[0];
    const int NNZ = in_sizes[3];
    const int N   = in_sizes[7] / HDIM;
    const int D   = out_size / 2;
    float* out = (float*)d_out;

    float *buf1, *buf2, *docH, *docH0, *hidden, *doc, *t2;
    int *Arp, *Awp, *Aci, *Xrp, *Xwp, *Xci;
    float *Av, *Xv;
    cudaGetSymbolAddress((void**)&buf1,   g_buf1);
    cudaGetSymbolAddress((void**)&buf2,   g_buf2);
    cudaGetSymbolAddress((void**)&docH,   g_docH);
    cudaGetSymbolAddress((void**)&docH0,  g_docH0);
    cudaGetSymbolAddress((void**)&hidden, g_hidden);
    cudaGetSymbolAddress((void**)&doc,    g_doc);
    cudaGetSymbolAddress((void**)&t2,     g_t2);
    cudaGetSymbolAddress((void**)&Arp, g_Arp);
    cudaGetSymbolAddress((void**)&Awp, g_Awp);
    cudaGetSymbolAddress((void**)&Aci, g_Aci);
    cudaGetSymbolAddress((void**)&Av,  g_Av);
    cudaGetSymbolAddress((void**)&Xrp, g_Xrp);
    cudaGetSymbolAddress((void**)&Xwp, g_Xwp);
    cudaGetSymbolAddress((void**)&Xci, g_Xci);
    cudaGetSymbolAddress((void**)&Xv,  g_Xv);

    const dim3 gblk(64, 4);
    const int  gcnGrid = (N + 31) / 32;
    const int  docGrid = (D + 31) / 32;

    // ---- build CSR for A (word graph) and X (tfidf) ----
    k_zero_i32<<<(N + 2 + 255) / 256, 256>>>(Arp, N + 1);
    k_hist    <<<(E + 255) / 256, 256>>>(A_rows, E, Arp);
    k_scan_excl<<<1, 1024>>>(Arp, N, Awp);
    k_scatter <<<(E + 255) / 256, 256>>>(A_rows, A_cols, A_vals, E, Awp, Aci, Av);

    k_zero_i32<<<(D + 2 + 255) / 256, 256>>>(Xrp, D + 1);
    k_hist    <<<(NNZ + 255) / 256, 256>>>(X_rows, NNZ, Xrp);
    k_scan_excl<<<1, 1024>>>(Xrp, D, Xwp);
    k_scatter <<<(NNZ + 255) / 256, 256>>>(X_rows, X_cols, X_vals, NNZ, Xwp, Xci, Xv);

    // ---- 3 residual GCN blocks ----
    k_spmm<<<N, 128>>>(Arp, Aci, Av, emb, buf1);
    k_gemm<HDIM, EPI_LN_GELU><<<gcnGrid, gblk>>>(buf1, nullptr, HDIM, HDIM,
        W1, nullptr, g1, b1, nullptr, nullptr, nullptr, buf2, N);

    k_spmm<<<N, 128>>>(Arp, Aci, Av, buf2, buf1);
    k_gemm<HDIM, EPI_LN_GELU><<<gcnGrid, gblk>>>(buf1, nullptr, HDIM, HDIM,
        W2, nullptr, g2, b2, nullptr, nullptr, nullptr, buf2, N);

    k_spmm<<<N, 128>>>(Arp, Aci, Av, buf2, buf1);
    // last block fuses word_H = 0.35*emb + 0.65*gelu(ln(...))
    k_gemm<HDIM, EPI_LN_GELU><<<gcnGrid, gblk>>>(buf1, nullptr, HDIM, HDIM,
        W3, nullptr, g3, b3, nullptr, nullptr, emb, buf2, N);

    // ---- doc aggregation ----
    k_spmm<<<D, 128>>>(Xrp, Xci, Xv, buf2, docH);
    k_spmm<<<D, 128>>>(Xrp, Xci, Xv, emb,  docH0);

    // gate hidden = gelu([docH | docH0] @ gate_W1 + gate_b1)
    k_gemm<HDIM, EPI_GELU><<<docGrid, gblk>>>(docH, docH0, 2 * HDIM, HDIM,
        gate_W1, gate_b1, nullptr, nullptr, nullptr, nullptr, nullptr, hidden, D);

    // gate = sigmoid(hidden @ gate_W2 + gate_b2); doc = gate*docH + (1-gate)*docH0
    k_gemm<HDIM, EPI_GATE><<<docGrid, gblk>>>(hidden, nullptr, HDIM, HDIM,
        gate_W2, gate_b2, nullptr, nullptr, docH, docH0, nullptr, doc, D);

    // mlp1: ln(gelu(doc @ mlp_W1 + mlp_b1))
    k_gemm<HDIM, EPI_GELU_LN><<<docGrid, gblk>>>(doc, nullptr, HDIM, HDIM,
        mlp_W1, mlp_b1, mlp_g, mlp_bn, nullptr, nullptr, nullptr, hidden, D);

    // mlp2: gelu(hidden @ mlp_W2 + mlp_b2) -> [D, 192]
    k_gemm<HHALF, EPI_GELU><<<docGrid, gblk>>>(hidden, nullptr, HDIM, HDIM,
        mlp_W2, mlp_b2, nullptr, nullptr, nullptr, nullptr, nullptr, t2, D);

    // logits
    k_logits<<<(D + 7) / 8, 256>>>(t2, cls_W, cls_b, out, D);
}

// round 3
// speedup vs baseline: 2.0231x; 2.0231x over previous
#include <cuda_runtime.h>
#include <math.h>
#include <stdint.h>

// ---------------- problem constants ----------------
#define HDIM  384
#define HHALF 192
constexpr int   MAXN   = 40000;
constexpr int   MAXD   = 20000;
constexpr int   MAXE   = 800000;
constexpr int   MAXNNZ = 800000;
constexpr float ALPHA  = 0.65f;
constexpr float LN_EPS = 1e-5f;

// ---------------- static scratch ----------------
__device__ float g_buf1[(size_t)MAXN * HDIM];
__device__ float g_buf2[(size_t)MAXN * HDIM];
__device__ float g_docH [(size_t)MAXD * HDIM];
__device__ float g_docH0[(size_t)MAXD * HDIM];
__device__ float g_hidden[(size_t)MAXD * HDIM];
__device__ float g_doc  [(size_t)MAXD * HDIM];
__device__ float g_t2   [(size_t)MAXD * HHALF];

__device__ int   g_Arp[MAXN + 1];
__device__ int   g_Awp[MAXN + 1];
__device__ int   g_Aci[MAXE];
__device__ float g_Av [MAXE];
__device__ int   g_Xrp[MAXD + 1];
__device__ int   g_Xwp[MAXD + 1];
__device__ int   g_Xci[MAXNNZ];
__device__ float g_Xv [MAXNNZ];

// ---------------- helpers ----------------
__device__ __forceinline__ float gelu_exact(float x) {
    return 0.5f * x * (1.0f + erff(x * 0.70710678118654752f));
}
__device__ __forceinline__ float sigmoidf_(float x) {
    return 1.0f / (1.0f + __expf(-x));
}
__device__ __forceinline__ void tf32_split(float v, uint32_t& hi, uint32_t& lo) {
    uint32_t h;
    asm("cvt.rna.tf32.f32 %0, %1;" : "=r"(h) : "f"(v));
    hi = h;
    lo = __float_as_uint(v - __uint_as_float(h));
}
__device__ __forceinline__ void mma_tf32(float* d, const uint32_t* a, const uint32_t* b) {
    asm volatile(
        "mma.sync.aligned.m16n8k8.row.col.f32.tf32.tf32.f32 "
        "{%0,%1,%2,%3}, {%4,%5,%6,%7}, {%8,%9}, {%0,%1,%2,%3};"
        : "+f"(d[0]), "+f"(d[1]), "+f"(d[2]), "+f"(d[3])
        : "r"(a[0]), "r"(a[1]), "r"(a[2]), "r"(a[3]), "r"(b[0]), "r"(b[1]));
}

// ---------------- CSR build ----------------
__global__ void k_zero_i32(int* p, int n) {
    int i = blockIdx.x * blockDim.x + threadIdx.x;
    if (i < n) p[i] = 0;
}

__global__ void k_hist(const int* __restrict__ rows, int ne, int* __restrict__ cnt) {
    int e = blockIdx.x * blockDim.x + threadIdx.x;
    if (e < ne) atomicAdd(&cnt[rows[e]], 1);
}

__global__ void k_scan_excl(int* __restrict__ data, int n, int* __restrict__ wp) {
    __shared__ int sums[1024];
    int t = threadIdx.x;
    int C = (n + 1023) / 1024;
    int start = t * C;
    int end   = min(start + C, n);

    int s = 0;
    for (int i = start; i < end; i++) s += data[i];
    sums[t] = s;
    __syncthreads();

    for (int off = 1; off < 1024; off <<= 1) {
        int add = (t >= off) ? sums[t - off] : 0;
        __syncthreads();
        sums[t] += add;
        __syncthreads();
    }

    int run = sums[t] - s;
    for (int i = start; i < end; i++) {
        int c = data[i];
        data[i] = run;
        wp[i]   = run;
        run += c;
    }
    if (t == 1023) data[n] = sums[1023];
}

__global__ void k_scatter(const int* __restrict__ rows, const int* __restrict__ cols,
                          const float* __restrict__ vals, int ne,
                          int* __restrict__ wp, int* __restrict__ ci,
                          float* __restrict__ cv) {
    int e = blockIdx.x * blockDim.x + threadIdx.x;
    if (e < ne) {
        int pos = atomicAdd(&wp[rows[e]], 1);
        ci[pos] = cols[e];
        cv[pos] = vals[e];
    }
}

// ---------------- SpMM (CSR gather) ----------------
__global__ void k_spmm(const int* __restrict__ rp, const int* __restrict__ ci,
                       const float* __restrict__ cv, const float* __restrict__ M,
                       float* __restrict__ out) {
    int r = blockIdx.x;
    int t = threadIdx.x;
    int s = rp[r], e = rp[r + 1];
    float a0 = 0.f, a1 = 0.f, a2 = 0.f;
    for (int j = s; j < e; j++) {
        float v = cv[j];
        const float* m = M + (size_t)ci[j] * HDIM;
        a0 = fmaf(v, m[t],       a0);
        a1 = fmaf(v, m[t + 128], a1);
        a2 = fmaf(v, m[t + 256], a2);
    }
    float* o = out + (size_t)r * HDIM;
    o[t] = a0; o[t + 128] = a1; o[t + 256] = a2;
}

// ---------------- tensor-core GEMM (split-tf32) with fused epilogues ----------------
// C[M x NCOLS] = epilogue( A[M x K] @ W[K x NCOLS] ), A may be virtual concat [A1|A2].
// block tile 64 x NCOLS; warp tile 32 x 48 (2x6 m16n8k8); BK=16; reg-staged prefetch.
enum { EPI_LN_GELU = 0, EPI_GELU = 1, EPI_GATE = 2, EPI_GELU_LN = 3 };

template <int NCOLS, int EPI>
__global__ void __launch_bounds__(64 * (NCOLS / 48))
k_gemm(const float* __restrict__ A1, const float* __restrict__ A2,
       int K, int K1,
       const float* __restrict__ W, const float* __restrict__ bias,
       const float* __restrict__ gw, const float* __restrict__ bw,
       const float* __restrict__ aux1, const float* __restrict__ aux2,
       const float* __restrict__ res,
       float* __restrict__ out, int M) {
    constexpr int NWN     = NCOLS / 48;        // warps along N (8 or 4)
    constexpr int THREADS = 64 * NWN;          // 512 or 256
    constexpr int BM = 64, BK = 16;
    constexpr int MT = 2, NT = 6;
    constexpr int AV4 = BM * BK / 4;           // 256 float4
    constexpr int BV4 = BK * NCOLS / 4;        // 1536 or 768
    constexpr int AITER = (AV4 + THREADS - 1) / THREADS;  // 1
    constexpr int BITER = BV4 / THREADS;                  // 3

    __shared__ float As[BM][BK + 4];
    __shared__ float Bs[BK][NCOLS + 8];
    __shared__ float redS[2][32][8];
    __shared__ float redQ[2][32][8];

    const int tid  = threadIdx.x;
    const int lane = tid & 31;
    const int warp = tid >> 5;
    const int wm = warp & 1;       // 0..1 along M
    const int wn = warp >> 1;      // 0..NWN-1 along N
    const int g  = lane >> 2;      // group 0..7
    const int t  = lane & 3;       // thread-in-group 0..3
    const int bm0 = blockIdx.x * BM;
    const int NC  = K / BK;

    float acc[MT][NT][4];
#pragma unroll
    for (int mt = 0; mt < MT; mt++)
#pragma unroll
        for (int nt = 0; nt < NT; nt++)
#pragma unroll
            for (int c = 0; c < 4; c++) acc[mt][nt][c] = 0.f;

    float4 pa[AITER];
    float4 pb[BITER];

    auto gload = [&](int k0) {
        const float* Ab;
        int kc, AW;
        if (k0 < K1) { Ab = A1; kc = k0; AW = K1; }
        else         { Ab = A2; kc = k0 - K1; AW = K - K1; }
#pragma unroll
        for (int i = 0; i < AITER; i++) {
            int idx = tid + i * THREADS;
            if (idx < AV4) {
                int row = idx >> 2, f4 = idx & 3;
                int grow = bm0 + row;
                if (grow < M)
                    pa[i] = *(const float4*)(Ab + (size_t)grow * AW + kc + 4 * f4);
                else
                    pa[i] = make_float4(0.f, 0.f, 0.f, 0.f);
            }
        }
#pragma unroll
        for (int i = 0; i < BITER; i++) {
            int idx = tid + i * THREADS;
            int kk = idx / (NCOLS / 4), n4 = idx % (NCOLS / 4);
            pb[i] = *(const float4*)(W + (size_t)(k0 + kk) * NCOLS + 4 * n4);
        }
    };
    auto sstore = [&]() {
#pragma unroll
        for (int i = 0; i < AITER; i++) {
            int idx = tid + i * THREADS;
            if (idx < AV4) {
                int row = idx >> 2, f4 = idx & 3;
                *(float4*)&As[row][4 * f4] = pa[i];
            }
        }
#pragma unroll
        for (int i = 0; i < BITER; i++) {
            int idx = tid + i * THREADS;
            int kk = idx / (NCOLS / 4), n4 = idx % (NCOLS / 4);
            *(float4*)&Bs[kk][4 * n4] = pb[i];
        }
    };

    gload(0);
    sstore();
    __syncthreads();

    for (int c = 0; c < NC; c++) {
        if (c + 1 < NC) gload((c + 1) * BK);

#pragma unroll
        for (int kk = 0; kk < 2; kk++) {
            const int k8 = kk * 8;
            uint32_t ahi[MT][4], alo[MT][4];
#pragma unroll
            for (int mt = 0; mt < MT; mt++) {
                int r0 = wm * 32 + mt * 16;
                float a0 = As[r0 + g][k8 + t];
                float a1 = As[r0 + g + 8][k8 + t];
                float a2 = As[r0 + g][k8 + t + 4];
                float a3 = As[r0 + g + 8][k8 + t + 4];
                tf32_split(a0, ahi[mt][0], alo[mt][0]);
                tf32_split(a1, ahi[mt][1], alo[mt][1]);
                tf32_split(a2, ahi[mt][2], alo[mt][2]);
                tf32_split(a3, ahi[mt][3], alo[mt][3]);
            }
#pragma unroll
            for (int nt = 0; nt < NT; nt++) {
                int n0 = wn * 48 + nt * 8;
                float b0 = Bs[k8 + t][n0 + g];
                float b1 = Bs[k8 + t + 4][n0 + g];
                uint32_t bh[2], bl[2];
                tf32_split(b0, bh[0], bl[0]);
                tf32_split(b1, bh[1], bl[1]);
#pragma unroll
                for (int mt = 0; mt < MT; mt++) {
                    mma_tf32(acc[mt][nt], ahi[mt], bh);
                    mma_tf32(acc[mt][nt], alo[mt], bh);
                    mma_tf32(acc[mt][nt], ahi[mt], bl);
                }
            }
        }
        __syncthreads();
        if (c + 1 < NC) {
            sstore();
            __syncthreads();
        }
    }

    // -------- epilogues --------
    // acc[mt][nt][c]: row = wm*32 + mt*16 + 8*(c>>1) + g ; col = wn*48 + nt*8 + 2*t + (c&1)

    if constexpr (EPI == EPI_GELU) {
#pragma unroll
        for (int mt = 0; mt < MT; mt++)
#pragma unroll
            for (int d = 0; d < 2; d++) {
                int grow = bm0 + wm * 32 + mt * 16 + 8 * d + g;
                if (grow >= M) continue;
#pragma unroll
                for (int nt = 0; nt < NT; nt++) {
                    int col = wn * 48 + nt * 8 + 2 * t;
                    float v0 = acc[mt][nt][2 * d]     + (bias ? bias[col]     : 0.f);
                    float v1 = acc[mt][nt][2 * d + 1] + (bias ? bias[col + 1] : 0.f);
                    *(float2*)&out[(size_t)grow * NCOLS + col] =
                        make_float2(gelu_exact(v0), gelu_exact(v1));
                }
            }
    } else if constexpr (EPI == EPI_GATE) {
#pragma unroll
        for (int mt = 0; mt < MT; mt++)
#pragma unroll
            for (int d = 0; d < 2; d++) {
                int grow = bm0 + wm * 32 + mt * 16 + 8 * d + g;
                if (grow >= M) continue;
#pragma unroll
                for (int nt = 0; nt < NT; nt++) {
                    int col = wn * 48 + nt * 8 + 2 * t;
                    size_t idx = (size_t)grow * NCOLS + col;
                    float s0 = sigmoidf_(acc[mt][nt][2 * d]     + bias[col]);
                    float s1 = sigmoidf_(acc[mt][nt][2 * d + 1] + bias[col + 1]);
                    float2 h1 = *(const float2*)&aux1[idx];
                    float2 h0 = *(const float2*)&aux2[idx];
                    *(float2*)&out[idx] = make_float2(
                        s0 * h1.x + (1.f - s0) * h0.x,
                        s1 * h1.y + (1.f - s1) * h0.y);
                }
            }
    } else {
        // LayerNorm epilogues: stats over full NCOLS row
        float sm_[MT][2], sq_[MT][2];
#pragma unroll
        for (int mt = 0; mt < MT; mt++)
#pragma unroll
            for (int d = 0; d < 2; d++) { sm_[mt][d] = 0.f; sq_[mt][d] = 0.f; }

#pragma unroll
        for (int mt = 0; mt < MT; mt++)
#pragma unroll
            for (int nt = 0; nt < NT; nt++) {
                int col = wn * 48 + nt * 8 + 2 * t;
#pragma unroll
                for (int d = 0; d < 2; d++) {
                    float v0 = acc[mt][nt][2 * d];
                    float v1 = acc[mt][nt][2 * d + 1];
                    if constexpr (EPI == EPI_GELU_LN) {
                        v0 = gelu_exact(v0 + bias[col]);
                        v1 = gelu_exact(v1 + bias[col + 1]);
                        acc[mt][nt][2 * d] = v0;
                        acc[mt][nt][2 * d + 1] = v1;
                    }
                    sm_[mt][d] += v0 + v1;
                    sq_[mt][d] += v0 * v0 + v1 * v1;
                }
            }
        // reduce over t (lanes differing in bits 0-1)
#pragma unroll
        for (int mt = 0; mt < MT; mt++)
#pragma unroll
            for (int d = 0; d < 2; d++) {
                float s = sm_[mt][d], q = sq_[mt][d];
                s += __shfl_xor_sync(0xffffffffu, s, 1);
                q += __shfl_xor_sync(0xffffffffu, q, 1);
                s += __shfl_xor_sync(0xffffffffu, s, 2);
                q += __shfl_xor_sync(0xffffffffu, q, 2);
                sm_[mt][d] = s; sq_[mt][d] = q;
            }
        if (t == 0) {
#pragma unroll
            for (int mt = 0; mt < MT; mt++)
#pragma unroll
                for (int d = 0; d < 2; d++) {
                    int rr = mt * 16 + 8 * d + g;
                    redS[wm][rr][wn] = sm_[mt][d];
                    redQ[wm][rr][wn] = sq_[mt][d];
                }
        }
        __syncthreads();
#pragma unroll
        for (int mt = 0; mt < MT; mt++)
#pragma unroll
            for (int d = 0; d < 2; d++) {
                int rr = mt * 16 + 8 * d + g;
                float S = 0.f, Q = 0.f;
#pragma unroll
                for (int w = 0; w < NWN; w++) { S += redS[wm][rr][w]; Q += redQ[wm][rr][w]; }
                float mean = S * (1.0f / NCOLS);
                float var  = Q * (1.0f / NCOLS) - mean * mean;
                float rstd = rsqrtf(var + LN_EPS);
                int grow = bm0 + wm * 32 + rr;
                if (grow >= M) continue;
#pragma unroll
                for (int nt = 0; nt < NT; nt++) {
                    int col = wn * 48 + nt * 8 + 2 * t;
                    float nv0 = (acc[mt][nt][2 * d]     - mean) * rstd * gw[col]     + bw[col];
                    float nv1 = (acc[mt][nt][2 * d + 1] - mean) * rstd * gw[col + 1] + bw[col + 1];
                    float o0, o1;
                    if constexpr (EPI == EPI_LN_GELU) {
                        o0 = gelu_exact(nv0);
                        o1 = gelu_exact(nv1);
                        if (res) {
                            float2 rv = *(const float2*)&res[(size_t)grow * NCOLS + col];
                            o0 = (1.f - ALPHA) * rv.x + ALPHA * o0;
                            o1 = (1.f - ALPHA) * rv.y + ALPHA * o1;
                        }
                    } else {
                        o0 = nv0; o1 = nv1;
                    }
                    *(float2*)&out[(size_t)grow * NCOLS + col] = make_float2(o0, o1);
                }
            }
    }
}

// ---------------- final tiny classifier ----------------
__global__ void k_logits(const float* __restrict__ t2, const float* __restrict__ clsW,
                         const float* __restrict__ clsb, float* __restrict__ out, int D) {
    int warp = (blockIdx.x * blockDim.x + threadIdx.x) >> 5;
    int lane = threadIdx.x & 31;
    if (warp >= D) return;
    const float* r = t2 + (size_t)warp * HHALF;
    float a0 = 0.f, a1 = 0.f;
    for (int k = lane; k < HHALF; k += 32) {
        float x = r[k];
        a0 = fmaf(x, clsW[2 * k],     a0);
        a1 = fmaf(x, clsW[2 * k + 1], a1);
    }
    for (int off = 16; off > 0; off >>= 1) {
        a0 += __shfl_down_sync(0xffffffffu, a0, off);
        a1 += __shfl_down_sync(0xffffffffu, a1, off);
    }
    if (lane == 0) {
        out[2 * warp]     = a0 + clsb[0];
        out[2 * warp + 1] = a1 + clsb[1];
    }
}

// ---------------- launch ----------------
extern "C" void kernel_launch(void* const* d_in, const int* in_sizes, int n_in,
                              void* d_out, int out_size) {
    const int*   A_rows  = (const int*)  d_in[0];
    const int*   A_cols  = (const int*)  d_in[1];
    const float* A_vals  = (const float*)d_in[2];
    const int*   X_rows  = (const int*)  d_in[3];
    const int*   X_cols  = (const int*)  d_in[4];
    const float* X_vals  = (const float*)d_in[5];
    const float* emb     = (const float*)d_in[7];
    const float* W1      = (const float*)d_in[8];
    const float* W2      = (const float*)d_in[9];
    const float* W3      = (const float*)d_in[10];
    const float* g1      = (const float*)d_in[11];
    const float* b1      = (const float*)d_in[12];
    const float* g2      = (const float*)d_in[13];
    const float* b2      = (const float*)d_in[14];
    const float* g3      = (const float*)d_in[15];
    const float* b3      = (const float*)d_in[16];
    const float* mlp_W1  = (const float*)d_in[17];
    const float* mlp_b1  = (const float*)d_in[18];
    const float* mlp_g   = (const float*)d_in[19];
    const float* mlp_bn  = (const float*)d_in[20];
    const float* mlp_W2  = (const float*)d_in[21];
    const float* mlp_b2  = (const float*)d_in[22];
    const float* cls_W   = (const float*)d_in[23];
    const float* cls_b   = (const float*)d_in[24];
    const float* gate_W1 = (const float*)d_in[25];
    const float* gate_b1 = (const float*)d_in[26];
    const float* gate_W2 = (const float*)d_in[27];
    const float* gate_b2 = (const float*)d_in[28];

    const int E   = in_sizes[0];
    const int NNZ = in_sizes[3];
    const int N   = in_sizes[7] / HDIM;
    const int D   = out_size / 2;
    float* out = (float*)d_out;

    float *buf1, *buf2, *docH, *docH0, *hidden, *doc, *t2;
    int *Arp, *Awp, *Aci, *Xrp, *Xwp, *Xci;
    float *Av, *Xv;
    cudaGetSymbolAddress((void**)&buf1,   g_buf1);
    cudaGetSymbolAddress((void**)&buf2,   g_buf2);
    cudaGetSymbolAddress((void**)&docH,   g_docH);
    cudaGetSymbolAddress((void**)&docH0,  g_docH0);
    cudaGetSymbolAddress((void**)&hidden, g_hidden);
    cudaGetSymbolAddress((void**)&doc,    g_doc);
    cudaGetSymbolAddress((void**)&t2,     g_t2);
    cudaGetSymbolAddress((void**)&Arp, g_Arp);
    cudaGetSymbolAddress((void**)&Awp, g_Awp);
    cudaGetSymbolAddress((void**)&Aci, g_Aci);
    cudaGetSymbolAddress((void**)&Av,  g_Av);
    cudaGetSymbolAddress((void**)&Xrp, g_Xrp);
    cudaGetSymbolAddress((void**)&Xwp, g_Xwp);
    cudaGetSymbolAddress((void**)&Xci, g_Xci);
    cudaGetSymbolAddress((void**)&Xv,  g_Xv);

    const int gcnGrid = (N + 63) / 64;
    const int docGrid = (D + 63) / 64;

    // ---- build CSR for A and X ----
    k_zero_i32<<<(N + 2 + 255) / 256, 256>>>(Arp, N + 1);
    k_hist    <<<(E + 255) / 256, 256>>>(A_rows, E, Arp);
    k_scan_excl<<<1, 1024>>>(Arp, N, Awp);
    k_scatter <<<(E + 255) / 256, 256>>>(A_rows, A_cols, A_vals, E, Awp, Aci, Av);

    k_zero_i32<<<(D + 2 + 255) / 256, 256>>>(Xrp, D + 1);
    k_hist    <<<(NNZ + 255) / 256, 256>>>(X_rows, NNZ, Xrp);
    k_scan_excl<<<1, 1024>>>(Xrp, D, Xwp);
    k_scatter <<<(NNZ + 255) / 256, 256>>>(X_rows, X_cols, X_vals, NNZ, Xwp, Xci, Xv);

    // ---- 3 residual GCN blocks ----
    k_spmm<<<N, 128>>>(Arp, Aci, Av, emb, buf1);
    k_gemm<HDIM, EPI_LN_GELU><<<gcnGrid, 512>>>(buf1, nullptr, HDIM, HDIM,
        W1, nullptr, g1, b1, nullptr, nullptr, nullptr, buf2, N);

    k_spmm<<<N, 128>>>(Arp, Aci, Av, buf2, buf1);
    k_gemm<HDIM, EPI_LN_GELU><<<gcnGrid, 512>>>(buf1, nullptr, HDIM, HDIM,
        W2, nullptr, g2, b2, nullptr, nullptr, nullptr, buf2, N);

    k_spmm<<<N, 128>>>(Arp, Aci, Av, buf2, buf1);
    k_gemm<HDIM, EPI_LN_GELU><<<gcnGrid, 512>>>(buf1, nullptr, HDIM, HDIM,
        W3, nullptr, g3, b3, nullptr, nullptr, emb, buf2, N);

    // ---- doc aggregation ----
    k_spmm<<<D, 128>>>(Xrp, Xci, Xv, buf2, docH);
    k_spmm<<<D, 128>>>(Xrp, Xci, Xv, emb,  docH0);

    // gate hidden = gelu([docH | docH0] @ gate_W1 + gate_b1)
    k_gemm<HDIM, EPI_GELU><<<docGrid, 512>>>(docH, docH0, 2 * HDIM, HDIM,
        gate_W1, gate_b1, nullptr, nullptr, nullptr, nullptr, nullptr, hidden, D);

    // gate = sigmoid(hidden @ gate_W2 + gate_b2); doc = gate*docH + (1-gate)*docH0
    k_gemm<HDIM, EPI_GATE><<<docGrid, 512>>>(hidden, nullptr, HDIM, HDIM,
        gate_W2, gate_b2, nullptr, nullptr, docH, docH0, nullptr, doc, D);

    // mlp1: ln(gelu(doc @ mlp_W1 + mlp_b1))
    k_gemm<HDIM, EPI_GELU_LN><<<docGrid, 512>>>(doc, nullptr, HDIM, HDIM,
        mlp_W1, mlp_b1, mlp_g, mlp_bn, nullptr, nullptr, nullptr, hidden, D);

    // mlp2: gelu(hidden @ mlp_W2 + mlp_b2) -> [D, 192]
    k_gemm<HHALF, EPI_GELU><<<docGrid, 256>>>(hidden, nullptr, HDIM, HDIM,
        mlp_W2, mlp_b2, nullptr, nullptr, nullptr, nullptr, nullptr, t2, D);

    // logits
    k_logits<<<(D + 7) / 8, 256>>>(t2, cls_W, cls_b, out, D);
}

// round 4
// speedup vs baseline: 2.1403x; 1.0579x over previous
#include <cuda_runtime.h>
#include <math.h>
#include <stdint.h>

// ---------------- problem constants ----------------
#define HDIM  384
#define HHALF 192
constexpr int   MAXN   = 40000;
constexpr int   MAXD   = 20000;
constexpr int   MAXE   = 800000;
constexpr int   MAXNNZ = 800000;
constexpr float ALPHA  = 0.65f;
constexpr float LN_EPS = 1e-5f;

// ---------------- static scratch ----------------
__device__ float g_buf1[(size_t)MAXN * HDIM];
__device__ float g_buf2[(size_t)MAXN * HDIM];
__device__ float g_docH [(size_t)MAXD * HDIM];
__device__ float g_docH0[(size_t)MAXD * HDIM];
__device__ float g_hidden[(size_t)MAXD * HDIM];
__device__ float g_doc  [(size_t)MAXD * HDIM];
__device__ float g_t2   [(size_t)MAXD * HHALF];

__device__ int   g_Arp[MAXN + 1];
__device__ int   g_Awp[MAXN + 1];
__device__ int   g_Aci[MAXE];
__device__ float g_Av [MAXE];
__device__ int   g_Xrp[MAXD + 1];
__device__ int   g_Xwp[MAXD + 1];
__device__ int   g_Xci[MAXNNZ];
__device__ float g_Xv [MAXNNZ];

// ---------------- helpers ----------------
__device__ __forceinline__ float gelu_exact(float x) {
    return 0.5f * x * (1.0f + erff(x * 0.70710678118654752f));
}
__device__ __forceinline__ float sigmoidf_(float x) {
    return 1.0f / (1.0f + __expf(-x));
}
__device__ __forceinline__ void tf32_split(float v, uint32_t& hi, uint32_t& lo) {
    uint32_t h;
    asm("cvt.rna.tf32.f32 %0, %1;" : "=r"(h) : "f"(v));
    hi = h;
    lo = __float_as_uint(v - __uint_as_float(h));
}
__device__ __forceinline__ void mma_tf32(float* d, const uint32_t* a, const uint32_t* b) {
    asm volatile(
        "mma.sync.aligned.m16n8k8.row.col.f32.tf32.tf32.f32 "
        "{%0,%1,%2,%3}, {%4,%5,%6,%7}, {%8,%9}, {%0,%1,%2,%3};"
        : "+f"(d[0]), "+f"(d[1]), "+f"(d[2]), "+f"(d[3])
        : "r"(a[0]), "r"(a[1]), "r"(a[2]), "r"(a[3]), "r"(b[0]), "r"(b[1]));
}
__device__ __forceinline__ void fma4(float4& a, float v, const float4& m) {
    a.x = fmaf(v, m.x, a.x);
    a.y = fmaf(v, m.y, a.y);
    a.z = fmaf(v, m.z, a.z);
    a.w = fmaf(v, m.w, a.w);
}

// ---------------- CSR build ----------------
__global__ void k_zero_i32(int* p, int n) {
    int i = blockIdx.x * blockDim.x + threadIdx.x;
    if (i < n) p[i] = 0;
}

__global__ void k_hist(const int* __restrict__ rows, int ne, int* __restrict__ cnt) {
    int e = blockIdx.x * blockDim.x + threadIdx.x;
    if (e < ne) atomicAdd(&cnt[rows[e]], 1);
}

__global__ void k_scan_excl(int* __restrict__ data, int n, int* __restrict__ wp) {
    __shared__ int sums[1024];
    int t = threadIdx.x;
    int C = (n + 1023) / 1024;
    int start = t * C;
    int end   = min(start + C, n);

    int s = 0;
    for (int i = start; i < end; i++) s += data[i];
    sums[t] = s;
    __syncthreads();

    for (int off = 1; off < 1024; off <<= 1) {
        int add = (t >= off) ? sums[t - off] : 0;
        __syncthreads();
        sums[t] += add;
        __syncthreads();
    }

    int run = sums[t] - s;
    for (int i = start; i < end; i++) {
        int c = data[i];
        data[i] = run;
        wp[i]   = run;
        run += c;
    }
    if (t == 1023) data[n] = sums[1023];
}

__global__ void k_scatter(const int* __restrict__ rows, const int* __restrict__ cols,
                          const float* __restrict__ vals, int ne,
                          int* __restrict__ wp, int* __restrict__ ci,
                          float* __restrict__ cv) {
    int e = blockIdx.x * blockDim.x + threadIdx.x;
    if (e < ne) {
        int pos = atomicAdd(&wp[rows[e]], 1);
        ci[pos] = cols[e];
        cv[pos] = vals[e];
    }
}

// ---------------- SpMM (CSR gather, float4, unroll-4) ----------------
// 96 threads per block, one output row per block; thread t owns float4 column t.
__global__ void __launch_bounds__(96)
k_spmm(const int* __restrict__ rp, const int* __restrict__ ci,
       const float* __restrict__ cv, const float* __restrict__ M,
       float* __restrict__ out) {
    const int r = blockIdx.x;
    const int t = threadIdx.x;
    const int s = rp[r], e = rp[r + 1];
    const float4* __restrict__ M4 = (const float4*)M;
    float4 acc = make_float4(0.f, 0.f, 0.f, 0.f);

    int j = s;
    for (; j + 4 <= e; j += 4) {
        int   c0 = ci[j],     c1 = ci[j + 1], c2 = ci[j + 2], c3 = ci[j + 3];
        float v0 = cv[j],     v1 = cv[j + 1], v2 = cv[j + 2], v3 = cv[j + 3];
        float4 m0 = M4[(size_t)c0 * 96 + t];
        float4 m1 = M4[(size_t)c1 * 96 + t];
        float4 m2 = M4[(size_t)c2 * 96 + t];
        float4 m3 = M4[(size_t)c3 * 96 + t];
        fma4(acc, v0, m0);
        fma4(acc, v1, m1);
        fma4(acc, v2, m2);
        fma4(acc, v3, m3);
    }
    for (; j < e; j++) {
        float4 m = M4[(size_t)ci[j] * 96 + t];
        fma4(acc, cv[j], m);
    }
    ((float4*)(out + (size_t)r * HDIM))[t] = acc;
}

// fused double-SpMM: gathers from two dense matrices with the same CSR.
__global__ void __launch_bounds__(96)
k_spmm2(const int* __restrict__ rp, const int* __restrict__ ci,
        const float* __restrict__ cv,
        const float* __restrict__ Ma, const float* __restrict__ Mb,
        float* __restrict__ outA, float* __restrict__ outB) {
    const int r = blockIdx.x;
    const int t = threadIdx.x;
    const int s = rp[r], e = rp[r + 1];
    const float4* __restrict__ A4 = (const float4*)Ma;
    const float4* __restrict__ B4 = (const float4*)Mb;
    float4 accA = make_float4(0.f, 0.f, 0.f, 0.f);
    float4 accB = make_float4(0.f, 0.f, 0.f, 0.f);

    int j = s;
    for (; j + 2 <= e; j += 2) {
        int   c0 = ci[j],  c1 = ci[j + 1];
        float v0 = cv[j],  v1 = cv[j + 1];
        float4 a0 = A4[(size_t)c0 * 96 + t];
        float4 b0 = B4[(size_t)c0 * 96 + t];
        float4 a1 = A4[(size_t)c1 * 96 + t];
        float4 b1 = B4[(size_t)c1 * 96 + t];
        fma4(accA, v0, a0);
        fma4(accB, v0, b0);
        fma4(accA, v1, a1);
        fma4(accB, v1, b1);
    }
    for (; j < e; j++) {
        int   c = ci[j];
        float v = cv[j];
        float4 a = A4[(size_t)c * 96 + t];
        float4 b = B4[(size_t)c * 96 + t];
        fma4(accA, v, a);
        fma4(accB, v, b);
    }
    ((float4*)(outA + (size_t)r * HDIM))[t] = accA;
    ((float4*)(outB + (size_t)r * HDIM))[t] = accB;
}

// ---------------- tensor-core GEMM (split-tf32) with fused epilogues ----------------
enum { EPI_LN_GELU = 0, EPI_GELU = 1, EPI_GATE = 2, EPI_GELU_LN = 3 };

template <int NCOLS, int EPI>
__global__ void __launch_bounds__(64 * (NCOLS / 48))
k_gemm(const float* __restrict__ A1, const float* __restrict__ A2,
       int K, int K1,
       const float* __restrict__ W, const float* __restrict__ bias,
       const float* __restrict__ gw, const float* __restrict__ bw,
       const float* __restrict__ aux1, const float* __restrict__ aux2,
       const float* __restrict__ res,
       float* __restrict__ out, int M) {
    constexpr int NWN     = NCOLS / 48;
    constexpr int THREADS = 64 * NWN;
    constexpr int BM = 64, BK = 16;
    constexpr int MT = 2, NT = 6;
    constexpr int AV4 = BM * BK / 4;
    constexpr int BV4 = BK * NCOLS / 4;
    constexpr int AITER = (AV4 + THREADS - 1) / THREADS;
    constexpr int BITER = BV4 / THREADS;

    __shared__ float As[BM][BK + 4];
    __shared__ float Bs[BK][NCOLS + 8];
    __shared__ float redS[2][32][8];
    __shared__ float redQ[2][32][8];

    const int tid  = threadIdx.x;
    const int lane = tid & 31;
    const int warp = tid >> 5;
    const int wm = warp & 1;
    const int wn = warp >> 1;
    const int g  = lane >> 2;
    const int t  = lane & 3;
    const int bm0 = blockIdx.x * BM;
    const int NC  = K / BK;

    float acc[MT][NT][4];
#pragma unroll
    for (int mt = 0; mt < MT; mt++)
#pragma unroll
        for (int nt = 0; nt < NT; nt++)
#pragma unroll
            for (int c = 0; c < 4; c++) acc[mt][nt][c] = 0.f;

    float4 pa[AITER];
    float4 pb[BITER];

    auto gload = [&](int k0) {
        const float* Ab;
        int kc, AW;
        if (k0 < K1) { Ab = A1; kc = k0; AW = K1; }
        else         { Ab = A2; kc = k0 - K1; AW = K - K1; }
#pragma unroll
        for (int i = 0; i < AITER; i++) {
            int idx = tid + i * THREADS;
            if (idx < AV4) {
                int row = idx >> 2, f4 = idx & 3;
                int grow = bm0 + row;
                if (grow < M)
                    pa[i] = *(const float4*)(Ab + (size_t)grow * AW + kc + 4 * f4);
                else
                    pa[i] = make_float4(0.f, 0.f, 0.f, 0.f);
            }
        }
#pragma unroll
        for (int i = 0; i < BITER; i++) {
            int idx = tid + i * THREADS;
            int kk = idx / (NCOLS / 4), n4 = idx % (NCOLS / 4);
            pb[i] = *(const float4*)(W + (size_t)(k0 + kk) * NCOLS + 4 * n4);
        }
    };
    auto sstore = [&]() {
#pragma unroll
        for (int i = 0; i < AITER; i++) {
            int idx = tid + i * THREADS;
            if (idx < AV4) {
                int row = idx >> 2, f4 = idx & 3;
                *(float4*)&As[row][4 * f4] = pa[i];
            }
        }
#pragma unroll
        for (int i = 0; i < BITER; i++) {
            int idx = tid + i * THREADS;
            int kk = idx / (NCOLS / 4), n4 = idx % (NCOLS / 4);
            *(float4*)&Bs[kk][4 * n4] = pb[i];
        }
    };

    gload(0);
    sstore();
    __syncthreads();

    for (int c = 0; c < NC; c++) {
        if (c + 1 < NC) gload((c + 1) * BK);

#pragma unroll
        for (int kk = 0; kk < 2; kk++) {
            const int k8 = kk * 8;
            uint32_t ahi[MT][4], alo[MT][4];
#pragma unroll
            for (int mt = 0; mt < MT; mt++) {
                int r0 = wm * 32 + mt * 16;
                float a0 = As[r0 + g][k8 + t];
                float a1 = As[r0 + g + 8][k8 + t];
                float a2 = As[r0 + g][k8 + t + 4];
                float a3 = As[r0 + g + 8][k8 + t + 4];
                tf32_split(a0, ahi[mt][0], alo[mt][0]);
                tf32_split(a1, ahi[mt][1], alo[mt][1]);
                tf32_split(a2, ahi[mt][2], alo[mt][2]);
                tf32_split(a3, ahi[mt][3], alo[mt][3]);
            }
#pragma unroll
            for (int nt = 0; nt < NT; nt++) {
                int n0 = wn * 48 + nt * 8;
                float b0 = Bs[k8 + t][n0 + g];
                float b1 = Bs[k8 + t + 4][n0 + g];
                uint32_t bh[2], bl[2];
                tf32_split(b0, bh[0], bl[0]);
                tf32_split(b1, bh[1], bl[1]);
#pragma unroll
                for (int mt = 0; mt < MT; mt++) {
                    mma_tf32(acc[mt][nt], ahi[mt], bh);
                    mma_tf32(acc[mt][nt], alo[mt], bh);
                    mma_tf32(acc[mt][nt], ahi[mt], bl);
                }
            }
        }
        __syncthreads();
        if (c + 1 < NC) {
            sstore();
            __syncthreads();
        }
    }

    // -------- epilogues --------
    if constexpr (EPI == EPI_GELU) {
#pragma unroll
        for (int mt = 0; mt < MT; mt++)
#pragma unroll
            for (int d = 0; d < 2; d++) {
                int grow = bm0 + wm * 32 + mt * 16 + 8 * d + g;
                if (grow >= M) continue;
#pragma unroll
                for (int nt = 0; nt < NT; nt++) {
                    int col = wn * 48 + nt * 8 + 2 * t;
                    float v0 = acc[mt][nt][2 * d]     + (bias ? bias[col]     : 0.f);
                    float v1 = acc[mt][nt][2 * d + 1] + (bias ? bias[col + 1] : 0.f);
                    *(float2*)&out[(size_t)grow * NCOLS + col] =
                        make_float2(gelu_exact(v0), gelu_exact(v1));
                }
            }
    } else if constexpr (EPI == EPI_GATE) {
#pragma unroll
        for (int mt = 0; mt < MT; mt++)
#pragma unroll
            for (int d = 0; d < 2; d++) {
                int grow = bm0 + wm * 32 + mt * 16 + 8 * d + g;
                if (grow >= M) continue;
#pragma unroll
                for (int nt = 0; nt < NT; nt++) {
                    int col = wn * 48 + nt * 8 + 2 * t;
                    size_t idx = (size_t)grow * NCOLS + col;
                    float s0 = sigmoidf_(acc[mt][nt][2 * d]     + bias[col]);
                    float s1 = sigmoidf_(acc[mt][nt][2 * d + 1] + bias[col + 1]);
                    float2 h1 = *(const float2*)&aux1[idx];
                    float2 h0 = *(const float2*)&aux2[idx];
                    *(float2*)&out[idx] = make_float2(
                        s0 * h1.x + (1.f - s0) * h0.x,
                        s1 * h1.y + (1.f - s1) * h0.y);
                }
            }
    } else {
        float sm_[MT][2], sq_[MT][2];
#pragma unroll
        for (int mt = 0; mt < MT; mt++)
#pragma unroll
            for (int d = 0; d < 2; d++) { sm_[mt][d] = 0.f; sq_[mt][d] = 0.f; }

#pragma unroll
        for (int mt = 0; mt < MT; mt++)
#pragma unroll
            for (int nt = 0; nt < NT; nt++) {
                int col = wn * 48 + nt * 8 + 2 * t;
#pragma unroll
                for (int d = 0; d < 2; d++) {
                    float v0 = acc[mt][nt][2 * d];
                    float v1 = acc[mt][nt][2 * d + 1];
                    if constexpr (EPI == EPI_GELU_LN) {
                        v0 = gelu_exact(v0 + bias[col]);
                        v1 = gelu_exact(v1 + bias[col + 1]);
                        acc[mt][nt][2 * d] = v0;
                        acc[mt][nt][2 * d + 1] = v1;
                    }
                    sm_[mt][d] += v0 + v1;
                    sq_[mt][d] += v0 * v0 + v1 * v1;
                }
            }
#pragma unroll
        for (int mt = 0; mt < MT; mt++)
#pragma unroll
            for (int d = 0; d < 2; d++) {
                float s = sm_[mt][d], q = sq_[mt][d];
                s += __shfl_xor_sync(0xffffffffu, s, 1);
                q += __shfl_xor_sync(0xffffffffu, q, 1);
                s += __shfl_xor_sync(0xffffffffu, s, 2);
                q += __shfl_xor_sync(0xffffffffu, q, 2);
                sm_[mt][d] = s; sq_[mt][d] = q;
            }
        if (t == 0) {
#pragma unroll
            for (int mt = 0; mt < MT; mt++)
#pragma unroll
                for (int d = 0; d < 2; d++) {
                    int rr = mt * 16 + 8 * d + g;
                    redS[wm][rr][wn] = sm_[mt][d];
                    redQ[wm][rr][wn] = sq_[mt][d];
                }
        }
        __syncthreads();
#pragma unroll
        for (int mt = 0; mt < MT; mt++)
#pragma unroll
            for (int d = 0; d < 2; d++) {
                int rr = mt * 16 + 8 * d + g;
                float S = 0.f, Q = 0.f;
#pragma unroll
                for (int w = 0; w < NWN; w++) { S += redS[wm][rr][w]; Q += redQ[wm][rr][w]; }
                float mean = S * (1.0f / NCOLS);
                float var  = Q * (1.0f / NCOLS) - mean * mean;
                float rstd = rsqrtf(var + LN_EPS);
                int grow = bm0 + wm * 32 + rr;
                if (grow >= M) continue;
#pragma unroll
                for (int nt = 0; nt < NT; nt++) {
                    int col = wn * 48 + nt * 8 + 2 * t;
                    float nv0 = (acc[mt][nt][2 * d]     - mean) * rstd * gw[col]     + bw[col];
                    float nv1 = (acc[mt][nt][2 * d + 1] - mean) * rstd * gw[col + 1] + bw[col + 1];
                    float o0, o1;
                    if constexpr (EPI == EPI_LN_GELU) {
                        o0 = gelu_exact(nv0);
                        o1 = gelu_exact(nv1);
                        if (res) {
                            float2 rv = *(const float2*)&res[(size_t)grow * NCOLS + col];
                            o0 = (1.f - ALPHA) * rv.x + ALPHA * o0;
                            o1 = (1.f - ALPHA) * rv.y + ALPHA * o1;
                        }
                    } else {
                        o0 = nv0; o1 = nv1;
                    }
                    *(float2*)&out[(size_t)grow * NCOLS + col] = make_float2(o0, o1);
                }
            }
    }
}

// ---------------- final tiny classifier ----------------
__global__ void k_logits(const float* __restrict__ t2, const float* __restrict__ clsW,
                         const float* __restrict__ clsb, float* __restrict__ out, int D) {
    int warp = (blockIdx.x * blockDim.x + threadIdx.x) >> 5;
    int lane = threadIdx.x & 31;
    if (warp >= D) return;
    const float* r = t2 + (size_t)warp * HHALF;
    float a0 = 0.f, a1 = 0.f;
    for (int k = lane; k < HHALF; k += 32) {
        float x = r[k];
        a0 = fmaf(x, clsW[2 * k],     a0);
        a1 = fmaf(x, clsW[2 * k + 1], a1);
    }
    for (int off = 16; off > 0; off >>= 1) {
        a0 += __shfl_down_sync(0xffffffffu, a0, off);
        a1 += __shfl_down_sync(0xffffffffu, a1, off);
    }
    if (lane == 0) {
        out[2 * warp]     = a0 + clsb[0];
        out[2 * warp + 1] = a1 + clsb[1];
    }
}

// ---------------- launch ----------------
extern "C" void kernel_launch(void* const* d_in, const int* in_sizes, int n_in,
                              void* d_out, int out_size) {
    const int*   A_rows  = (const int*)  d_in[0];
    const int*   A_cols  = (const int*)  d_in[1];
    const float* A_vals  = (const float*)d_in[2];
    const int*   X_rows  = (const int*)  d_in[3];
    const int*   X_cols  = (const int*)  d_in[4];
    const float* X_vals  = (const float*)d_in[5];
    const float* emb     = (const float*)d_in[7];
    const float* W1      = (const float*)d_in[8];
    const float* W2      = (const float*)d_in[9];
    const float* W3      = (const float*)d_in[10];
    const float* g1      = (const float*)d_in[11];
    const float* b1      = (const float*)d_in[12];
    const float* g2      = (const float*)d_in[13];
    const float* b2      = (const float*)d_in[14];
    const float* g3      = (const float*)d_in[15];
    const float* b3      = (const float*)d_in[16];
    const float* mlp_W1  = (const float*)d_in[17];
    const float* mlp_b1  = (const float*)d_in[18];
    const float* mlp_g   = (const float*)d_in[19];
    const float* mlp_bn  = (const float*)d_in[20];
    const float* mlp_W2  = (const float*)d_in[21];
    const float* mlp_b2  = (const float*)d_in[22];
    const float* cls_W   = (const float*)d_in[23];
    const float* cls_b   = (const float*)d_in[24];
    const float* gate_W1 = (const float*)d_in[25];
    const float* gate_b1 = (const float*)d_in[26];
    const float* gate_W2 = (const float*)d_in[27];
    const float* gate_b2 = (const float*)d_in[28];

    const int E   = in_sizes[0];
    const int NNZ = in_sizes[3];
    const int N   = in_sizes[7] / HDIM;
    const int D   = out_size / 2;
    float* out = (float*)d_out;

    float *buf1, *buf2, *docH, *docH0, *hidden, *doc, *t2;
    int *Arp, *Awp, *Aci, *Xrp, *Xwp, *Xci;
    float *Av, *Xv;
    cudaGetSymbolAddress((void**)&buf1,   g_buf1);
    cudaGetSymbolAddress((void**)&buf2,   g_buf2);
    cudaGetSymbolAddress((void**)&docH,   g_docH);
    cudaGetSymbolAddress((void**)&docH0,  g_docH0);
    cudaGetSymbolAddress((void**)&hidden, g_hidden);
    cudaGetSymbolAddress((void**)&doc,    g_doc);
    cudaGetSymbolAddress((void**)&t2,     g_t2);
    cudaGetSymbolAddress((void**)&Arp, g_Arp);
    cudaGetSymbolAddress((void**)&Awp, g_Awp);
    cudaGetSymbolAddress((void**)&Aci, g_Aci);
    cudaGetSymbolAddress((void**)&Av,  g_Av);
    cudaGetSymbolAddress((void**)&Xrp, g_Xrp);
    cudaGetSymbolAddress((void**)&Xwp, g_Xwp);
    cudaGetSymbolAddress((void**)&Xci, g_Xci);
    cudaGetSymbolAddress((void**)&Xv,  g_Xv);

    const int gcnGrid = (N + 63) / 64;
    const int docGrid = (D + 63) / 64;

    // ---- build CSR for A and X ----
    k_zero_i32<<<(N + 2 + 255) / 256, 256>>>(Arp, N + 1);
    k_hist    <<<(E + 255) / 256, 256>>>(A_rows, E, Arp);
    k_scan_excl<<<1, 1024>>>(Arp, N, Awp);
    k_scatter <<<(E + 255) / 256, 256>>>(A_rows, A_cols, A_vals, E, Awp, Aci, Av);

    k_zero_i32<<<(D + 2 + 255) / 256, 256>>>(Xrp, D + 1);
    k_hist    <<<(NNZ + 255) / 256, 256>>>(X_rows, NNZ, Xrp);
    k_scan_excl<<<1, 1024>>>(Xrp, D, Xwp);
    k_scatter <<<(NNZ + 255) / 256, 256>>>(X_rows, X_cols, X_vals, NNZ, Xwp, Xci, Xv);

    // ---- 3 residual GCN blocks ----
    k_spmm<<<N, 96>>>(Arp, Aci, Av, emb, buf1);
    k_gemm<HDIM, EPI_LN_GELU><<<gcnGrid, 512>>>(buf1, nullptr, HDIM, HDIM,
        W1, nullptr, g1, b1, nullptr, nullptr, nullptr, buf2, N);

    k_spmm<<<N, 96>>>(Arp, Aci, Av, buf2, buf1);
    k_gemm<HDIM, EPI_LN_GELU><<<gcnGrid, 512>>>(buf1, nullptr, HDIM, HDIM,
        W2, nullptr, g2, b2, nullptr, nullptr, nullptr, buf2, N);

    k_spmm<<<N, 96>>>(Arp, Aci, Av, buf2, buf1);
    k_gemm<HDIM, EPI_LN_GELU><<<gcnGrid, 512>>>(buf1, nullptr, HDIM, HDIM,
        W3, nullptr, g3, b3, nullptr, nullptr, emb, buf2, N);

    // ---- doc aggregation (fused: docH from word_H, docH0 from emb) ----
    k_spmm2<<<D, 96>>>(Xrp, Xci, Xv, buf2, emb, docH, docH0);

    // gate hidden = gelu([docH | docH0] @ gate_W1 + gate_b1)
    k_gemm<HDIM, EPI_GELU><<<docGrid, 512>>>(docH, docH0, 2 * HDIM, HDIM,
        gate_W1, gate_b1, nullptr, nullptr, nullptr, nullptr, nullptr, hidden, D);

    // gate = sigmoid(hidden @ gate_W2 + gate_b2); doc = gate*docH + (1-gate)*docH0
    k_gemm<HDIM, EPI_GATE><<<docGrid, 512>>>(hidden, nullptr, HDIM, HDIM,
        gate_W2, gate_b2, nullptr, nullptr, docH, docH0, nullptr, doc, D);

    // mlp1: ln(gelu(doc @ mlp_W1 + mlp_b1))
    k_gemm<HDIM, EPI_GELU_LN><<<docGrid, 512>>>(doc, nullptr, HDIM, HDIM,
        mlp_W1, mlp_b1, mlp_g, mlp_bn, nullptr, nullptr, nullptr, hidden, D);

    // mlp2: gelu(hidden @ mlp_W2 + mlp_b2) -> [D, 192]
    k_gemm<HHALF, EPI_GELU><<<docGrid, 256>>>(hidden, nullptr, HDIM, HDIM,
        mlp_W2, mlp_b2, nullptr, nullptr, nullptr, nullptr, nullptr, t2, D);

    // logits
    k_logits<<<(D + 7) / 8, 256>>>(t2, cls_W, cls_b, out, D);
}

// round 6
// speedup vs baseline: 2.8748x; 1.3432x over previous
#include <cuda_runtime.h>
#include <math.h>
#include <stdint.h>

// ---------------- problem constants ----------------
#define HDIM  384
#define HHALF 192
constexpr int   MAXN   = 40000;
constexpr int   MAXD   = 20000;
constexpr int   MAXE   = 800000;
constexpr int   MAXNNZ = 800000;
constexpr float ALPHA  = 0.65f;
constexpr float LN_EPS = 1e-5f;

// weight split pool offsets (u32 units, layout [K/2][NCOLS])
constexpr int OFF_W1  = 0;
constexpr int OFF_W2  = 73728;
constexpr int OFF_W3  = 147456;
constexpr int OFF_GW2 = 221184;
constexpr int OFF_MW1 = 294912;
constexpr int OFF_GW1 = 368640;   // 384x384 u32 (K=768)
constexpr int OFF_MW2 = 516096;   // 192x192 u32
constexpr int WPOOL   = 552960;

// ---------------- static scratch ----------------
__device__ float g_buf1[(size_t)MAXN * HDIM];
__device__ float g_buf2[(size_t)MAXN * HDIM];
__device__ float g_docH [(size_t)MAXD * HDIM];
__device__ float g_docH0[(size_t)MAXD * HDIM];
__device__ float g_hidden[(size_t)MAXD * HDIM];
__device__ float g_doc  [(size_t)MAXD * HDIM];
__device__ float g_t2   [(size_t)MAXD * HHALF];

__device__ __align__(16) uint32_t g_Whi[WPOOL];
__device__ __align__(16) uint32_t g_Wlo[WPOOL];

__device__ int   g_Arp[MAXN + 1];
__device__ int   g_Awp[MAXN + 1];
__device__ int   g_Aci[MAXE];
__device__ float g_Av [MAXE];
__device__ int   g_Xrp[MAXD + 1];
__device__ int   g_Xwp[MAXD + 1];
__device__ int   g_Xci[MAXNNZ];
__device__ float g_Xv [MAXNNZ];

// ---------------- helpers ----------------
__device__ __forceinline__ float gelu_exact(float x) {
    return 0.5f * x * (1.0f + erff(x * 0.70710678118654752f));
}
__device__ __forceinline__ float sigmoidf_(float x) {
    return 1.0f / (1.0f + __expf(-x));
}
// pack two floats into bf16x2: lo -> low half, hi -> high half
__device__ __forceinline__ uint32_t cvtbf2(float lo, float hi) {
    uint32_t r;
    asm("cvt.rn.bf16x2.f32 %0, %1, %2;" : "=r"(r) : "f"(hi), "f"(lo));
    return r;
}
__device__ __forceinline__ float bflo(uint32_t p) { return __uint_as_float(p << 16); }
__device__ __forceinline__ float bfhi(uint32_t p) { return __uint_as_float(p & 0xffff0000u); }
// split (x, y) into bf16x2 hi part + bf16x2 residual part
__device__ __forceinline__ void bsplit2(float x, float y, uint32_t& h, uint32_t& l) {
    h = cvtbf2(x, y);
    l = cvtbf2(x - bflo(h), y - bfhi(h));
}
__device__ __forceinline__ void mma_bf16(float* d, const uint32_t* a, const uint32_t* b) {
    asm volatile(
        "mma.sync.aligned.m16n8k16.row.col.f32.bf16.bf16.f32 "
        "{%0,%1,%2,%3}, {%4,%5,%6,%7}, {%8,%9}, {%0,%1,%2,%3};"
        : "+f"(d[0]), "+f"(d[1]), "+f"(d[2]), "+f"(d[3])
        : "r"(a[0]), "r"(a[1]), "r"(a[2]), "r"(a[3]), "r"(b[0]), "r"(b[1]));
}
__device__ __forceinline__ void fma4(float4& a, float v, const float4& m) {
    a.x = fmaf(v, m.x, a.x);
    a.y = fmaf(v, m.y, a.y);
    a.z = fmaf(v, m.z, a.z);
    a.w = fmaf(v, m.w, a.w);
}

// ---------------- weight pre-split: W[K][NC] -> hi/lo u32[K/2][NC] ----------------
__global__ void k_wsplit(const float* __restrict__ W, int KP, int NC,
                         uint32_t* __restrict__ hi, uint32_t* __restrict__ lo) {
    int idx = blockIdx.x * blockDim.x + threadIdx.x;
    if (idx >= KP * NC) return;
    int kp = idx / NC, n = idx - kp * NC;
    float x = W[(size_t)(2 * kp) * NC + n];
    float y = W[(size_t)(2 * kp + 1) * NC + n];
    uint32_t h, l;
    bsplit2(x, y, h, l);
    hi[idx] = h;
    lo[idx] = l;
}

// ---------------- CSR build ----------------
__global__ void k_zero_i32(int* p, int n) {
    int i = blockIdx.x * blockDim.x + threadIdx.x;
    if (i < n) p[i] = 0;
}

__global__ void k_hist(const int* __restrict__ rows, int ne, int* __restrict__ cnt) {
    int e = blockIdx.x * blockDim.x + threadIdx.x;
    if (e < ne) atomicAdd(&cnt[rows[e]], 1);
}

__global__ void k_scan_excl(int* __restrict__ data, int n, int* __restrict__ wp) {
    __shared__ int sums[1024];
    int t = threadIdx.x;
    int C = (n + 1023) / 1024;
    int start = t * C;
    int end   = min(start + C, n);

    int s = 0;
    for (int i = start; i < end; i++) s += data[i];
    sums[t] = s;
    __syncthreads();

    for (int off = 1; off < 1024; off <<= 1) {
        int add = (t >= off) ? sums[t - off] : 0;
        __syncthreads();
        sums[t] += add;
        __syncthreads();
    }

    int run = sums[t] - s;
    for (int i = start; i < end; i++) {
        int c = data[i];
        data[i] = run;
        wp[i]   = run;
        run += c;
    }
    if (t == 1023) data[n] = sums[1023];
}

__global__ void k_scatter(const int* __restrict__ rows, const int* __restrict__ cols,
                          const float* __restrict__ vals, int ne,
                          int* __restrict__ wp, int* __restrict__ ci,
                          float* __restrict__ cv) {
    int e = blockIdx.x * blockDim.x + threadIdx.x;
    if (e < ne) {
        int pos = atomicAdd(&wp[rows[e]], 1);
        ci[pos] = cols[e];
        cv[pos] = vals[e];
    }
}

// ---------------- SpMM (CSR gather, float4, unroll-4) ----------------
__global__ void __launch_bounds__(96)
k_spmm(const int* __restrict__ rp, const int* __restrict__ ci,
       const float* __restrict__ cv, const float* __restrict__ M,
       float* __restrict__ out) {
    const int r = blockIdx.x;
    const int t = threadIdx.x;
    const int s = rp[r], e = rp[r + 1];
    const float4* __restrict__ M4 = (const float4*)M;
    float4 acc = make_float4(0.f, 0.f, 0.f, 0.f);

    int j = s;
    for (; j + 4 <= e; j += 4) {
        int   c0 = ci[j],     c1 = ci[j + 1], c2 = ci[j + 2], c3 = ci[j + 3];
        float v0 = cv[j],     v1 = cv[j + 1], v2 = cv[j + 2], v3 = cv[j + 3];
        float4 m0 = M4[(size_t)c0 * 96 + t];
        float4 m1 = M4[(size_t)c1 * 96 + t];
        float4 m2 = M4[(size_t)c2 * 96 + t];
        float4 m3 = M4[(size_t)c3 * 96 + t];
        fma4(acc, v0, m0);
        fma4(acc, v1, m1);
        fma4(acc, v2, m2);
        fma4(acc, v3, m3);
    }
    for (; j < e; j++) {
        float4 m = M4[(size_t)ci[j] * 96 + t];
        fma4(acc, cv[j], m);
    }
    ((float4*)(out + (size_t)r * HDIM))[t] = acc;
}

__global__ void __launch_bounds__(96)
k_spmm2(const int* __restrict__ rp, const int* __restrict__ ci,
        const float* __restrict__ cv,
        const float* __restrict__ Ma, const float* __restrict__ Mb,
        float* __restrict__ outA, float* __restrict__ outB) {
    const int r = blockIdx.x;
    const int t = threadIdx.x;
    const int s = rp[r], e = rp[r + 1];
    const float4* __restrict__ A4 = (const float4*)Ma;
    const float4* __restrict__ B4 = (const float4*)Mb;
    float4 accA = make_float4(0.f, 0.f, 0.f, 0.f);
    float4 accB = make_float4(0.f, 0.f, 0.f, 0.f);

    int j = s;
    for (; j + 2 <= e; j += 2) {
        int   c0 = ci[j],  c1 = ci[j + 1];
        float v0 = cv[j],  v1 = cv[j + 1];
        float4 a0 = A4[(size_t)c0 * 96 + t];
        float4 b0 = B4[(size_t)c0 * 96 + t];
        float4 a1 = A4[(size_t)c1 * 96 + t];
        float4 b1 = B4[(size_t)c1 * 96 + t];
        fma4(accA, v0, a0);
        fma4(accB, v0, b0);
        fma4(accA, v1, a1);
        fma4(accB, v1, b1);
    }
    for (; j < e; j++) {
        int   c = ci[j];
        float v = cv[j];
        float4 a = A4[(size_t)c * 96 + t];
        float4 b = B4[(size_t)c * 96 + t];
        fma4(accA, v, a);
        fma4(accB, v, b);
    }
    ((float4*)(outA + (size_t)r * HDIM))[t] = accA;
    ((float4*)(outB + (size_t)r * HDIM))[t] = accB;
}

// ---------------- bf16x2 split tensor-core GEMM with fused epilogues ----------------
// C[M x NCOLS] = epilogue( A[M x K] @ W[K x NCOLS] ), A may be virtual concat [A1|A2].
// Weights pre-split into bf16x2 hi/lo, layout [K/2][NCOLS] (k-pairs packed).
// block tile 64 x NCOLS; warp tile 32 x 48 (2x6 m16n8k16); BK=16; 3-pass split.
enum { EPI_LN_GELU = 0, EPI_GELU = 1, EPI_GATE = 2, EPI_GELU_LN = 3 };

template <int NCOLS, int EPI>
__global__ void __launch_bounds__(64 * (NCOLS / 48))
k_gemm(const float* __restrict__ A1, const float* __restrict__ A2,
       int K, int K1,
       const uint32_t* __restrict__ Whi, const uint32_t* __restrict__ Wlo,
       const float* __restrict__ bias,
       const float* __restrict__ gw, const float* __restrict__ bw,
       const float* __restrict__ aux1, const float* __restrict__ aux2,
       const float* __restrict__ res,
       float* __restrict__ out, int M) {
    constexpr int NWN     = NCOLS / 48;
    constexpr int THREADS = 64 * NWN;
    constexpr int BM = 64, BK = 16;
    constexpr int MT = 2, NT = 6;
    constexpr int AV4 = BM * BK / 4;              // 256 float4
    constexpr int BU4 = (8 * NCOLS) / 4;          // uint4 per hi (or lo) tile
    constexpr int BITER = (BU4 + THREADS - 1) / THREADS;

    __shared__ uint32_t AsH[BM][12], AsL[BM][12];        // k-pairs, stride 12 = conflict-free
    __shared__ uint32_t BsH[8][NCOLS + 8], BsL[8][NCOLS + 8];
    __shared__ float redS[2][32][8];
    __shared__ float redQ[2][32][8];

    const int tid  = threadIdx.x;
    const int lane = tid & 31;
    const int warp = tid >> 5;
    const int wm = warp & 1;
    const int wn = warp >> 1;
    const int g  = lane >> 2;
    const int t  = lane & 3;
    const int bm0 = blockIdx.x * BM;
    const int NC  = K / BK;

    float acc[MT][NT][4];
#pragma unroll
    for (int mt = 0; mt < MT; mt++)
#pragma unroll
        for (int nt = 0; nt < NT; nt++)
#pragma unroll
            for (int c = 0; c < 4; c++) acc[mt][nt][c] = 0.f;

    float4 pa;
    uint4  pbh[BITER], pbl[BITER];

    auto gload = [&](int k0) {
        const float* Ab;
        int kc, AW;
        if (k0 < K1) { Ab = A1; kc = k0; AW = K1; }
        else         { Ab = A2; kc = k0 - K1; AW = K - K1; }
        if (tid < AV4) {
            int row = tid >> 2, f4 = tid & 3;
            int grow = bm0 + row;
            if (grow < M)
                pa = *(const float4*)(Ab + (size_t)grow * AW + kc + 4 * f4);
            else
                pa = make_float4(0.f, 0.f, 0.f, 0.f);
        }
        const uint4* bh = (const uint4*)(Whi + (size_t)(k0 / 2) * NCOLS);
        const uint4* bl = (const uint4*)(Wlo + (size_t)(k0 / 2) * NCOLS);
#pragma unroll
        for (int i = 0; i < BITER; i++) {
            int idx = tid + i * THREADS;
            if (idx < BU4) {
                pbh[i] = bh[idx];
                pbl[i] = bl[idx];
            }
        }
    };
    auto sstore = [&]() {
        if (tid < AV4) {
            int row = tid >> 2, f4 = tid & 3;
            uint32_t h0, l0, h1, l1;
            bsplit2(pa.x, pa.y, h0, l0);
            bsplit2(pa.z, pa.w, h1, l1);
            AsH[row][2 * f4]     = h0;
            AsH[row][2 * f4 + 1] = h1;
            AsL[row][2 * f4]     = l0;
            AsL[row][2 * f4 + 1] = l1;
        }
#pragma unroll
        for (int i = 0; i < BITER; i++) {
            int idx = tid + i * THREADS;
            if (idx < BU4) {
                int off = 4 * idx;
                int r = off / NCOLS, n = off - r * NCOLS;
                *(uint4*)&BsH[r][n] = pbh[i];
                *(uint4*)&BsL[r][n] = pbl[i];
            }
        }
    };

    gload(0);
    sstore();
    __syncthreads();

    for (int c = 0; c < NC; c++) {
        if (c + 1 < NC) gload((c + 1) * BK);

        uint32_t ah[MT][4], al[MT][4];
#pragma unroll
        for (int mt = 0; mt < MT; mt++) {
            int r0 = wm * 32 + mt * 16;
            ah[mt][0] = AsH[r0 + g][t];
            ah[mt][1] = AsH[r0 + g + 8][t];
            ah[mt][2] = AsH[r0 + g][t + 4];
            ah[mt][3] = AsH[r0 + g + 8][t + 4];
            al[mt][0] = AsL[r0 + g][t];
            al[mt][1] = AsL[r0 + g + 8][t];
            al[mt][2] = AsL[r0 + g][t + 4];
            al[mt][3] = AsL[r0 + g + 8][t + 4];
        }
#pragma unroll
        for (int nt = 0; nt < NT; nt++) {
            int n0 = wn * 48 + nt * 8 + g;
            uint32_t bh[2], bl[2];
            bh[0] = BsH[t][n0];
            bh[1] = BsH[t + 4][n0];
            bl[0] = BsL[t][n0];
            bl[1] = BsL[t + 4][n0];
#pragma unroll
            for (int mt = 0; mt < MT; mt++) {
                mma_bf16(acc[mt][nt], ah[mt], bh);
                mma_bf16(acc[mt][nt], al[mt], bh);
                mma_bf16(acc[mt][nt], ah[mt], bl);
            }
        }
        __syncthreads();
        if (c + 1 < NC) {
            sstore();
            __syncthreads();
        }
    }

    // -------- epilogues --------
    // acc[mt][nt][c]: row = wm*32 + mt*16 + 8*(c>>1) + g ; col = wn*48 + nt*8 + 2*t + (c&1)
    if constexpr (EPI == EPI_GELU) {
#pragma unroll
        for (int mt = 0; mt < MT; mt++)
#pragma unroll
            for (int d = 0; d < 2; d++) {
                int grow = bm0 + wm * 32 + mt * 16 + 8 * d + g;
                if (grow >= M) continue;
#pragma unroll
                for (int nt = 0; nt < NT; nt++) {
                    int col = wn * 48 + nt * 8 + 2 * t;
                    float v0 = acc[mt][nt][2 * d]     + (bias ? bias[col]     : 0.f);
                    float v1 = acc[mt][nt][2 * d + 1] + (bias ? bias[col + 1] : 0.f);
                    *(float2*)&out[(size_t)grow * NCOLS + col] =
                        make_float2(gelu_exact(v0), gelu_exact(v1));
                }
            }
    } else if constexpr (EPI == EPI_GATE) {
#pragma unroll
        for (int mt = 0; mt < MT; mt++)
#pragma unroll
            for (int d = 0; d < 2; d++) {
                int grow = bm0 + wm * 32 + mt * 16 + 8 * d + g;
                if (grow >= M) continue;
#pragma unroll
                for (int nt = 0; nt < NT; nt++) {
                    int col = wn * 48 + nt * 8 + 2 * t;
                    size_t idx = (size_t)grow * NCOLS + col;
                    float s0 = sigmoidf_(acc[mt][nt][2 * d]     + bias[col]);
                    float s1 = sigmoidf_(acc[mt][nt][2 * d + 1] + bias[col + 1]);
                    float2 h1 = *(const float2*)&aux1[idx];
                    float2 h0 = *(const float2*)&aux2[idx];
                    *(float2*)&out[idx] = make_float2(
                        s0 * h1.x + (1.f - s0) * h0.x,
                        s1 * h1.y + (1.f - s1) * h0.y);
                }
            }
    } else {
        float sm_[MT][2], sq_[MT][2];
#pragma unroll
        for (int mt = 0; mt < MT; mt++)
#pragma unroll
            for (int d = 0; d < 2; d++) { sm_[mt][d] = 0.f; sq_[mt][d] = 0.f; }

#pragma unroll
        for (int mt = 0; mt < MT; mt++)
#pragma unroll
            for (int nt = 0; nt < NT; nt++) {
                int col = wn * 48 + nt * 8 + 2 * t;
#pragma unroll
                for (int d = 0; d < 2; d++) {
                    float v0 = acc[mt][nt][2 * d];
                    float v1 = acc[mt][nt][2 * d + 1];
                    if constexpr (EPI == EPI_GELU_LN) {
                        v0 = gelu_exact(v0 + bias[col]);
                        v1 = gelu_exact(v1 + bias[col + 1]);
                        acc[mt][nt][2 * d] = v0;
                        acc[mt][nt][2 * d + 1] = v1;
                    }
                    sm_[mt][d] += v0 + v1;
                    sq_[mt][d] += v0 * v0 + v1 * v1;
                }
            }
#pragma unroll
        for (int mt = 0; mt < MT; mt++)
#pragma unroll
            for (int d = 0; d < 2; d++) {
                float s = sm_[mt][d], q = sq_[mt][d];
                s += __shfl_xor_sync(0xffffffffu, s, 1);
                q += __shfl_xor_sync(0xffffffffu, q, 1);
                s += __shfl_xor_sync(0xffffffffu, s, 2);
                q += __shfl_xor_sync(0xffffffffu, q, 2);
                sm_[mt][d] = s; sq_[mt][d] = q;
            }
        if (t == 0) {
#pragma unroll
            for (int mt = 0; mt < MT; mt++)
#pragma unroll
                for (int d = 0; d < 2; d++) {
                    int rr = mt * 16 + 8 * d + g;
                    redS[wm][rr][wn] = sm_[mt][d];
                    redQ[wm][rr][wn] = sq_[mt][d];
                }
        }
        __syncthreads();
#pragma unroll
        for (int mt = 0; mt < MT; mt++)
#pragma unroll
            for (int d = 0; d < 2; d++) {
                int rr = mt * 16 + 8 * d + g;
                float S = 0.f, Q = 0.f;
#pragma unroll
                for (int w = 0; w < NWN; w++) { S += redS[wm][rr][w]; Q += redQ[wm][rr][w]; }
                float mean = S * (1.0f / NCOLS);
                float var  = Q * (1.0f / NCOLS) - mean * mean;
                float rstd = rsqrtf(var + LN_EPS);
                int grow = bm0 + wm * 32 + rr;
                if (grow >= M) continue;
#pragma unroll
                for (int nt = 0; nt < NT; nt++) {
                    int col = wn * 48 + nt * 8 + 2 * t;
                    float nv0 = (acc[mt][nt][2 * d]     - mean) * rstd * gw[col]     + bw[col];
                    float nv1 = (acc[mt][nt][2 * d + 1] - mean) * rstd * gw[col + 1] + bw[col + 1];
                    float o0, o1;
                    if constexpr (EPI == EPI_LN_GELU) {
                        o0 = gelu_exact(nv0);
                        o1 = gelu_exact(nv1);
                        if (res) {
                            float2 rv = *(const float2*)&res[(size_t)grow * NCOLS + col];
                            o0 = (1.f - ALPHA) * rv.x + ALPHA * o0;
                            o1 = (1.f - ALPHA) * rv.y + ALPHA * o1;
                        }
                    } else {
                        o0 = nv0; o1 = nv1;
                    }
                    *(float2*)&out[(size_t)grow * NCOLS + col] = make_float2(o0, o1);
                }
            }
    }
}

// ---------------- final tiny classifier ----------------
__global__ void k_logits(const float* __restrict__ t2, const float* __restrict__ clsW,
                         const float* __restrict__ clsb, float* __restrict__ out, int D) {
    int warp = (blockIdx.x * blockDim.x + threadIdx.x) >> 5;
    int lane = threadIdx.x & 31;
    if (warp >= D) return;
    const float* r = t2 + (size_t)warp * HHALF;
    float a0 = 0.f, a1 = 0.f;
    for (int k = lane; k < HHALF; k += 32) {
        float x = r[k];
        a0 = fmaf(x, clsW[2 * k],     a0);
        a1 = fmaf(x, clsW[2 * k + 1], a1);
    }
    for (int off = 16; off > 0; off >>= 1) {
        a0 += __shfl_down_sync(0xffffffffu, a0, off);
        a1 += __shfl_down_sync(0xffffffffu, a1, off);
    }
    if (lane == 0) {
        out[2 * warp]     = a0 + clsb[0];
        out[2 * warp + 1] = a1 + clsb[1];
    }
}

// ---------------- launch ----------------
extern "C" void kernel_launch(void* const* d_in, const int* in_sizes, int n_in,
                              void* d_out, int out_size) {
    const int*   A_rows  = (const int*)  d_in[0];
    const int*   A_cols  = (const int*)  d_in[1];
    const float* A_vals  = (const float*)d_in[2];
    const int*   X_rows  = (const int*)  d_in[3];
    const int*   X_cols  = (const int*)  d_in[4];
    const float* X_vals  = (const float*)d_in[5];
    const float* emb     = (const float*)d_in[7];
    const float* W1      = (const float*)d_in[8];
    const float* W2      = (const float*)d_in[9];
    const float* W3      = (const float*)d_in[10];
    const float* g1      = (const float*)d_in[11];
    const float* b1      = (const float*)d_in[12];
    const float* g2      = (const float*)d_in[13];
    const float* b2      = (const float*)d_in[14];
    const float* g3      = (const float*)d_in[15];
    const float* b3      = (const float*)d_in[16];
    const float* mlp_W1  = (const float*)d_in[17];
    const float* mlp_b1  = (const float*)d_in[18];
    const float* mlp_g   = (const float*)d_in[19];
    const float* mlp_bn  = (const float*)d_in[20];
    const float* mlp_W2  = (const float*)d_in[21];
    const float* mlp_b2  = (const float*)d_in[22];
    const float* cls_W   = (const float*)d_in[23];
    const float* cls_b   = (const float*)d_in[24];
    const float* gate_W1 = (const float*)d_in[25];
    const float* gate_b1 = (const float*)d_in[26];
    const float* gate_W2 = (const float*)d_in[27];
    const float* gate_b2 = (const float*)d_in[28];

    const int E   = in_sizes[0];
    const int NNZ = in_sizes[3];
    const int N   = in_sizes[7] / HDIM;
    const int D   = out_size / 2;
    float* out = (float*)d_out;

    float *buf1, *buf2, *docH, *docH0, *hidden, *doc, *t2;
    int *Arp, *Awp, *Aci, *Xrp, *Xwp, *Xci;
    float *Av, *Xv;
    uint32_t *Whi, *Wlo;
    cudaGetSymbolAddress((void**)&buf1,   g_buf1);
    cudaGetSymbolAddress((void**)&buf2,   g_buf2);
    cudaGetSymbolAddress((void**)&docH,   g_docH);
    cudaGetSymbolAddress((void**)&docH0,  g_docH0);
    cudaGetSymbolAddress((void**)&hidden, g_hidden);
    cudaGetSymbolAddress((void**)&doc,    g_doc);
    cudaGetSymbolAddress((void**)&t2,     g_t2);
    cudaGetSymbolAddress((void**)&Arp, g_Arp);
    cudaGetSymbolAddress((void**)&Awp, g_Awp);
    cudaGetSymbolAddress((void**)&Aci, g_Aci);
    cudaGetSymbolAddress((void**)&Av,  g_Av);
    cudaGetSymbolAddress((void**)&Xrp, g_Xrp);
    cudaGetSymbolAddress((void**)&Xwp, g_Xwp);
    cudaGetSymbolAddress((void**)&Xci, g_Xci);
    cudaGetSymbolAddress((void**)&Xv,  g_Xv);
    cudaGetSymbolAddress((void**)&Whi, g_Whi);
    cudaGetSymbolAddress((void**)&Wlo, g_Wlo);

    const int gcnGrid = (N + 63) / 64;
    const int docGrid = (D + 63) / 64;

    // ---- pre-split all weights into bf16x2 hi/lo (k-pair-major) ----
    {
        const int n384 = 192 * 384;  // KP*NC for 384x384
        k_wsplit<<<(n384 + 255) / 256, 256>>>(W1,      192, 384, Whi + OFF_W1,  Wlo + OFF_W1);
        k_wsplit<<<(n384 + 255) / 256, 256>>>(W2,      192, 384, Whi + OFF_W2,  Wlo + OFF_W2);
        k_wsplit<<<(n384 + 255) / 256, 256>>>(W3,      192, 384, Whi + OFF_W3,  Wlo + OFF_W3);
        k_wsplit<<<(n384 + 255) / 256, 256>>>(gate_W2, 192, 384, Whi + OFF_GW2, Wlo + OFF_GW2);
        k_wsplit<<<(n384 + 255) / 256, 256>>>(mlp_W1,  192, 384, Whi + OFF_MW1, Wlo + OFF_MW1);
        const int ngw1 = 384 * 384;  // K=768
        k_wsplit<<<(ngw1 + 255) / 256, 256>>>(gate_W1, 384, 384, Whi + OFF_GW1, Wlo + OFF_GW1);
        const int nmw2 = 96 * 192;   // K=192? no: mlp_W2 is 384x192 -> KP=192, NC=192
        (void)nmw2;
        k_wsplit<<<(192 * 192 + 255) / 256, 256>>>(mlp_W2, 192, 192, Whi + OFF_MW2, Wlo + OFF_MW2);
    }

    // ---- build CSR for A and X ----
    k_zero_i32<<<(N + 2 + 255) / 256, 256>>>(Arp, N + 1);
    k_hist    <<<(E + 255) / 256, 256>>>(A_rows, E, Arp);
    k_scan_excl<<<1, 1024>>>(Arp, N, Awp);
    k_scatter <<<(E + 255) / 256, 256>>>(A_rows, A_cols, A_vals, E, Awp, Aci, Av);

    k_zero_i32<<<(D + 2 + 255) / 256, 256>>>(Xrp, D + 1);
    k_hist    <<<(NNZ + 255) / 256, 256>>>(X_rows, NNZ, Xrp);
    k_scan_excl<<<1, 1024>>>(Xrp, D, Xwp);
    k_scatter <<<(NNZ + 255) / 256, 256>>>(X_rows, X_cols, X_vals, NNZ, Xwp, Xci, Xv);

    // ---- 3 residual GCN blocks ----
    k_spmm<<<N, 96>>>(Arp, Aci, Av, emb, buf1);
    k_gemm<HDIM, EPI_LN_GELU><<<gcnGrid, 512>>>(buf1, nullptr, HDIM, HDIM,
        Whi + OFF_W1, Wlo + OFF_W1, nullptr, g1, b1, nullptr, nullptr, nullptr, buf2, N);

    k_spmm<<<N, 96>>>(Arp, Aci, Av, buf2, buf1);
    k_gemm<HDIM, EPI_LN_GELU><<<gcnGrid, 512>>>(buf1, nullptr, HDIM, HDIM,
        Whi + OFF_W2, Wlo + OFF_W2, nullptr, g2, b2, nullptr, nullptr, nullptr, buf2, N);

    k_spmm<<<N, 96>>>(Arp, Aci, Av, buf2, buf1);
    k_gemm<HDIM, EPI_LN_GELU><<<gcnGrid, 512>>>(buf1, nullptr, HDIM, HDIM,
        Whi + OFF_W3, Wlo + OFF_W3, nullptr, g3, b3, nullptr, nullptr, emb, buf2, N);

    // ---- doc aggregation (fused: docH from word_H, docH0 from emb) ----
    k_spmm2<<<D, 96>>>(Xrp, Xci, Xv, buf2, emb, docH, docH0);

    // gate hidden = gelu([docH | docH0] @ gate_W1 + gate_b1)
    k_gemm<HDIM, EPI_GELU><<<docGrid, 512>>>(docH, docH0, 2 * HDIM, HDIM,
        Whi + OFF_GW1, Wlo + OFF_GW1, gate_b1, nullptr, nullptr, nullptr, nullptr, nullptr, hidden, D);

    // gate = sigmoid(hidden @ gate_W2 + gate_b2); doc = gate*docH + (1-gate)*docH0
    k_gemm<HDIM, EPI_GATE><<<docGrid, 512>>>(hidden, nullptr, HDIM, HDIM,
        Whi + OFF_GW2, Wlo + OFF_GW2, gate_b2, nullptr, nullptr, docH, docH0, nullptr, doc, D);

    // mlp1: ln(gelu(doc @ mlp_W1 + mlp_b1))
    k_gemm<HDIM, EPI_GELU_LN><<<docGrid, 512>>>(doc, nullptr, HDIM, HDIM,
        Whi + OFF_MW1, Wlo + OFF_MW1, mlp_b1, mlp_g, mlp_bn, nullptr, nullptr, nullptr, hidden, D);

    // mlp2: gelu(hidden @ mlp_W2 + mlp_b2) -> [D, 192]
    k_gemm<HHALF, EPI_GELU><<<docGrid, 256>>>(hidden, nullptr, HDIM, HDIM,
        Whi + OFF_MW2, Wlo + OFF_MW2, mlp_b2, nullptr, nullptr, nullptr, nullptr, nullptr, t2, D);

    // logits
    k_logits<<<(D + 7) / 8, 256>>>(t2, cls_W, cls_b, out, D);
}